// round 12
// baseline (speedup 1.0000x reference)
#include <cuda_runtime.h>
#include <cuda_fp16.h>
#include <math.h>
#include <stdint.h>

#define B_  512
#define XD  768
#define YD  128
#define H2_ 512
#define NPART 16
#define KS1 4          // gemm1 K-split (768/4 = 192)
#define KS2 8          // gemm2 K-split (512/8 = 64)
#define GRID 144

__device__ float  g_H[2][KS1][B_ * H2_];   // gemm1 raw partials
__device__ float  g_Q[2][KS2][B_ * YD];    // gemm2 raw partials
__device__ double g_SyP [NPART][YD];
__device__ double g_Sy2P[NPART][YD];
__device__ double g_pos_row[B_];
__device__ double g_all_row[B_];
__device__ unsigned g_ctr  = 0;
__device__ unsigned g_cnt1 = 0, g_sns1 = 0;
__device__ unsigned g_cnt2 = 0, g_sns2 = 0;

// ---------------- fp16 2-term split (Markidis): x = h + l ----------------
__device__ __forceinline__ void split_pack(float x0, float x1,
                                           uint32_t &hi, uint32_t &lo) {
    __half h0 = __float2half_rn(x0), h1 = __float2half_rn(x1);
    float r0 = x0 - __half2float(h0), r1 = x1 - __half2float(h1);
    __half l0 = __float2half_rn(r0), l1 = __float2half_rn(r1);
    __half2 H = __halves2half2(h0, h1), L = __halves2half2(l0, l1);
    hi = *(uint32_t*)&H; lo = *(uint32_t*)&L;
}

#define MMA16(c, A, B) \
    asm volatile("mma.sync.aligned.m16n8k16.row.col.f32.f16.f16.f32 " \
        "{%0,%1,%2,%3},{%4,%5,%6,%7},{%8,%9},{%0,%1,%2,%3};" \
        : "+f"((c)[0]), "+f"((c)[1]), "+f"((c)[2]), "+f"((c)[3]) \
        : "r"((A)[0]), "r"((A)[1]), "r"((A)[2]), "r"((A)[3]), \
          "r"((B)[0]), "r"((B)[1]))

// Sense-reversing grid barrier (safe across graph replays: count self-resets,
// sense is monotonic; spin is on sense, never on a resettable counter).
__device__ __forceinline__ void gbar(unsigned* cnt, unsigned* sns, unsigned target) {
    __syncthreads();
    if (threadIdx.x == 0) {
        volatile unsigned* vs = (volatile unsigned*)sns;
        unsigned s0 = *vs;
        __threadfence();
        unsigned old = atomicAdd(cnt, 1u);
        if (old == target - 1u) {
            *cnt = 0u;
            __threadfence();
            atomicAdd(sns, 1u);
        } else {
            while (*vs == s0) __nanosleep(32);
            __threadfence();
        }
    }
    __syncthreads();
}

// Shared fragment pool (u32):
//  Ah [2buf][8mt][32lane][4slot]  = 2048  @ 0
//  Al                              = 2048  @ 2048
//  Bh [2buf][16nt][32lane][2slot] = 2048  @ 4096
//  Bl                              = 2048  @ 6144
#define POOL_U32 8192

__global__ __launch_bounds__(512, 1) void k_fused(
    const float* __restrict__ X,   const float* __restrict__ Y,
    const float* __restrict__ w1m, const float* __restrict__ b1m,
    const float* __restrict__ w2m, const float* __restrict__ b2m,
    const float* __restrict__ w1l, const float* __restrict__ b1l,
    const float* __restrict__ w2l, const float* __restrict__ b2l,
    float* __restrict__ out, int out_size)
{
    __shared__ uint32_t pool[POOL_U32];
    uint32_t* Ah = pool;
    uint32_t* Al = pool + 2048;
    uint32_t* Bh = pool + 4096;
    uint32_t* Bl = pool + 6144;

    const int b   = blockIdx.x;
    const int tid = threadIdx.x;
    const int wid  = tid >> 5,  lane = tid & 31;
    const int wm   = wid >> 2,  wn   = wid & 3;
    const int lg   = lane >> 2, lt   = lane & 3;

    // common loader decompositions (used by both GEMM phases)
    const int ar = tid >> 2, akq = tid & 3;
    const int a_mt   = ar >> 4;
    const int a_slot = ((ar >> 3) & 1) + 2 * (akq >> 1);
    const int a_lane = 4 * (ar & 7) + 2 * (akq & 1);
    const int bkp = tid >> 6, bn2 = tid & 63;
    const int b_lt = bkp & 3, b_slot = bkp >> 2;

    // =============== PHASE 1: gemm1 partials + ystats ===============
    if (b >= 128) {
        const int p = b - 128;
        if (tid < YD) {
            const int d = tid;
            const int j0 = p * (B_ / NPART);
            double sy0 = 0, sy1 = 0, s20 = 0, s21 = 0;
            #pragma unroll 4
            for (int j = j0; j < j0 + B_ / NPART; j += 2) {
                double v0 = (double)Y[j * YD + d], v1 = (double)Y[(j + 1) * YD + d];
                sy0 += v0; s20 = fma(v0, v0, s20);
                sy1 += v1; s21 = fma(v1, v1, s21);
            }
            g_SyP[p][d] = sy0 + sy1; g_Sy2P[p][d] = s20 + s21;
        }
    } else {
        const int head = b & 1;
        const int ks   = (b >> 1) & 3;
        const int t4   = b >> 3;
        const int m0   = (t4 >> 2) * 128;
        const int n0   = (t4 & 3) * 128;
        const int kb   = ks * 192;
        const float* W = head ? w1l : w1m;
        float* P       = &g_H[head][ks][0];

        const float* Xp = X + (size_t)(m0 + ar) * XD + kb + akq * 4;
        const float* Wp = W + (size_t)(kb + 2 * bkp) * H2_ + n0 + 2 * bn2;

        float acc[2][4][4] = {};
        float4 xa; float2 w0, w1;

        #define P1_LOAD(ch) do { \
            xa = *(const float4*)(Xp + (ch) * 16); \
            w0 = *(const float2*)(Wp + (size_t)(ch) * 16 * H2_); \
            w1 = *(const float2*)(Wp + (size_t)(ch) * 16 * H2_ + H2_); \
        } while (0)

        #define P1_STAGE(bf) do { \
            uint32_t h01, l01, h23, l23; \
            split_pack(xa.x, xa.y, h01, l01); \
            split_pack(xa.z, xa.w, h23, l23); \
            int ai = (((bf) * 8 + a_mt) * 32 + a_lane) * 4 + a_slot; \
            Ah[ai] = h01; Ah[ai + 4] = h23; \
            Al[ai] = l01; Al[ai + 4] = l23; \
            _Pragma("unroll") \
            for (int j = 0; j < 2; j++) { \
                int n = 2 * bn2 + j; \
                int nt = n >> 3; \
                int pl = (4 * (n & 7) + b_lt) ^ (2 * (nt & 7)); \
                float vk0 = j ? w0.y : w0.x; \
                float vk1 = j ? w1.y : w1.x; \
                uint32_t bhv, blv; \
                split_pack(vk0, vk1, bhv, blv); \
                int bi = (((bf) * 16 + nt) * 32 + pl) * 2 + b_slot; \
                Bh[bi] = bhv; Bl[bi] = blv; \
            } \
        } while (0)

        P1_LOAD(0);
        P1_STAGE(0);
        P1_LOAD(1);
        __syncthreads();

        for (int ch = 0; ch < 12; ch++) {
            const int bfc = ch & 1;
            if (ch + 1 < 12) P1_STAGE((ch + 1) & 1);
            if (ch + 2 < 12) P1_LOAD(ch + 2);

            uint32_t Af[2][4], Afl[2][4];
            #pragma unroll
            for (int mf = 0; mf < 2; mf++) {
                int mt = wm * 2 + mf;
                int ab = ((bfc * 8 + mt) * 32 + lane) * 4;
                uint4 h = *(const uint4*)&Ah[ab];
                uint4 l = *(const uint4*)&Al[ab];
                Af [mf][0] = h.x; Af [mf][1] = h.y; Af [mf][2] = h.z; Af [mf][3] = h.w;
                Afl[mf][0] = l.x; Afl[mf][1] = l.y; Afl[mf][2] = l.z; Afl[mf][3] = l.w;
            }
            uint32_t Bf[4][2], Bfl[4][2];
            #pragma unroll
            for (int nf = 0; nf < 4; nf++) {
                int nt = wn * 4 + nf;
                int bb = ((bfc * 16 + nt) * 32 + (lane ^ (2 * (nt & 7)))) * 2;
                uint2 h = *(const uint2*)&Bh[bb];
                uint2 l = *(const uint2*)&Bl[bb];
                Bf [nf][0] = h.x; Bf [nf][1] = h.y;
                Bfl[nf][0] = l.x; Bfl[nf][1] = l.y;
            }
            #pragma unroll
            for (int mf = 0; mf < 2; mf++)
                #pragma unroll
                for (int nf = 0; nf < 4; nf++) {
                    MMA16(acc[mf][nf], Af[mf],  Bf[nf]);
                    MMA16(acc[mf][nf], Af[mf],  Bfl[nf]);
                    MMA16(acc[mf][nf], Afl[mf], Bf[nf]);
                }
            __syncthreads();
        }

        #pragma unroll
        for (int mf = 0; mf < 2; mf++) {
            int row0 = m0 + wm * 32 + mf * 16 + lg;
            #pragma unroll
            for (int nf = 0; nf < 4; nf++) {
                int col = n0 + wn * 32 + nf * 8 + lt * 2;
                *(float2*)(P + (size_t)row0 * H2_ + col)       = make_float2(acc[mf][nf][0], acc[mf][nf][1]);
                *(float2*)(P + (size_t)(row0 + 8) * H2_ + col) = make_float2(acc[mf][nf][2], acc[mf][nf][3]);
            }
        }
    }

    gbar(&g_cnt1, &g_sns1, GRID);

    // =============== PHASE 2: gemm2 partials ===============
    if (b < 64) {
        const int head = b & 1;
        const int ks   = (b >> 1) & 7;
        const int mti  = b >> 4;
        const int m0   = mti * 128;
        const int kb   = ks * 64;
        const float* Hb = &g_H[head][0][0];
        const float* b1 = head ? b1l : b1m;
        const float* W  = head ? w2l : w2m;
        float*       Q  = g_Q[head][ks];
        const size_t HS = (size_t)B_ * H2_;

        const size_t aoff = (size_t)(m0 + ar) * H2_ + kb + akq * 4;
        const float* Wp   = W + (size_t)(kb + 2 * bkp) * YD + 2 * bn2;

        float acc[2][4][4] = {};
        float4 hh0, hh1, hh2, hh3, bv4; float2 w0, w1;

        #define P2_LOAD(ch) do { \
            hh0 = *(const float4*)(Hb + 0 * HS + aoff + (ch) * 16); \
            hh1 = *(const float4*)(Hb + 1 * HS + aoff + (ch) * 16); \
            hh2 = *(const float4*)(Hb + 2 * HS + aoff + (ch) * 16); \
            hh3 = *(const float4*)(Hb + 3 * HS + aoff + (ch) * 16); \
            bv4 = *(const float4*)(b1 + kb + akq * 4 + (ch) * 16); \
            w0  = *(const float2*)(Wp + (size_t)(ch) * 16 * YD); \
            w1  = *(const float2*)(Wp + (size_t)(ch) * 16 * YD + YD); \
        } while (0)

        #define P2_STAGE(bf) do { \
            float e0 = fmaxf(hh0.x + hh1.x + hh2.x + hh3.x + bv4.x, 0.0f); \
            float e1 = fmaxf(hh0.y + hh1.y + hh2.y + hh3.y + bv4.y, 0.0f); \
            float e2 = fmaxf(hh0.z + hh1.z + hh2.z + hh3.z + bv4.z, 0.0f); \
            float e3 = fmaxf(hh0.w + hh1.w + hh2.w + hh3.w + bv4.w, 0.0f); \
            uint32_t h01, l01, h23, l23; \
            split_pack(e0, e1, h01, l01); \
            split_pack(e2, e3, h23, l23); \
            int ai = (((bf) * 8 + a_mt) * 32 + a_lane) * 4 + a_slot; \
            Ah[ai] = h01; Ah[ai + 4] = h23; \
            Al[ai] = l01; Al[ai + 4] = l23; \
            _Pragma("unroll") \
            for (int j = 0; j < 2; j++) { \
                int n = 2 * bn2 + j; \
                int nt = n >> 3; \
                int pl = (4 * (n & 7) + b_lt) ^ (2 * (nt & 7)); \
                float vk0 = j ? w0.y : w0.x; \
                float vk1 = j ? w1.y : w1.x; \
                uint32_t bhv, blv; \
                split_pack(vk0, vk1, bhv, blv); \
                int bi = (((bf) * 16 + nt) * 32 + pl) * 2 + b_slot; \
                Bh[bi] = bhv; Bl[bi] = blv; \
            } \
        } while (0)

        P2_LOAD(0);
        P2_STAGE(0);
        P2_LOAD(1);
        __syncthreads();

        for (int ch = 0; ch < 4; ch++) {
            const int bfc = ch & 1;
            if (ch + 1 < 4) P2_STAGE((ch + 1) & 1);
            if (ch + 2 < 4) P2_LOAD(ch + 2);

            uint32_t Af[2][4], Afl[2][4];
            #pragma unroll
            for (int mf = 0; mf < 2; mf++) {
                int mt = wm * 2 + mf;
                int ab = ((bfc * 8 + mt) * 32 + lane) * 4;
                uint4 h = *(const uint4*)&Ah[ab];
                uint4 l = *(const uint4*)&Al[ab];
                Af [mf][0] = h.x; Af [mf][1] = h.y; Af [mf][2] = h.z; Af [mf][3] = h.w;
                Afl[mf][0] = l.x; Afl[mf][1] = l.y; Afl[mf][2] = l.z; Afl[mf][3] = l.w;
            }
            uint32_t Bf[4][2], Bfl[4][2];
            #pragma unroll
            for (int nf = 0; nf < 4; nf++) {
                int nt = wn * 4 + nf;
                int bb = ((bfc * 16 + nt) * 32 + (lane ^ (2 * (nt & 7)))) * 2;
                uint2 h = *(const uint2*)&Bh[bb];
                uint2 l = *(const uint2*)&Bl[bb];
                Bf [nf][0] = h.x; Bf [nf][1] = h.y;
                Bfl[nf][0] = l.x; Bfl[nf][1] = l.y;
            }
            #pragma unroll
            for (int mf = 0; mf < 2; mf++)
                #pragma unroll
                for (int nf = 0; nf < 4; nf++) {
                    MMA16(acc[mf][nf], Af[mf],  Bf[nf]);
                    MMA16(acc[mf][nf], Af[mf],  Bfl[nf]);
                    MMA16(acc[mf][nf], Afl[mf], Bf[nf]);
                }
            __syncthreads();
        }

        #pragma unroll
        for (int mf = 0; mf < 2; mf++) {
            int row0 = m0 + wm * 32 + mf * 16 + lg;
            #pragma unroll
            for (int nf = 0; nf < 4; nf++) {
                int col = wn * 32 + nf * 8 + lt * 2;
                *(float2*)(Q + (size_t)row0 * YD + col)       = make_float2(acc[mf][nf][0], acc[mf][nf][1]);
                *(float2*)(Q + (size_t)(row0 + 8) * YD + col) = make_float2(acc[mf][nf][2], acc[mf][nf][3]);
            }
        }
    }

    gbar(&g_cnt2, &g_sns2, GRID);

    // =============== PHASE 3: rows + final scalar ===============
    if (b >= 32) return;
    {
        double* sSy  = (double*)pool;         // 128 doubles
        double* sSy2 = (double*)pool + 128;   // 128 doubles
        __shared__ bool s_last;

        if (tid < YD) {
            double s = 0.0, s2 = 0.0;
            #pragma unroll
            for (int p = 0; p < NPART; p++) { s += g_SyP[p][tid]; s2 += g_Sy2P[p][tid]; }
            sSy[tid] = s; sSy2[tid] = s2;
        }
        __syncthreads();

        const int i = b * 16 + wid;
        double pos = 0.0, row = 0.0;
        #pragma unroll
        for (int q = 0; q < 4; q++) {
            int d = q * 32 + lane;
            int idx = i * YD + d;
            float muf = b2m[d];
            float sf  = b2l[d];
            #pragma unroll
            for (int j = 0; j < KS2; j++) {
                muf += g_Q[0][j][idx];
                sf  += g_Q[1][j][idx];
            }
            float lvf = tanhf(sf);
            float ivf = expf(-lvf);
            float yf  = Y[idx];

            float dmy = muf - yf;
            pos += (double)fmaf(-0.5f * dmy * dmy, ivf, -0.5f * lvf);

            double mu = (double)muf;
            double tq = fma(mu, fma(512.0, mu, -2.0 * sSy[d]), sSy2[d]);
            row = fma(-0.5 * (double)ivf, tq, row);
            row = fma(-256.0, (double)lvf, row);
        }
        #pragma unroll
        for (int off = 16; off > 0; off >>= 1) {
            pos += __shfl_down_sync(0xffffffffu, pos, off);
            row += __shfl_down_sync(0xffffffffu, row, off);
        }
        if (lane == 0) {
            g_pos_row[i] = pos;
            g_all_row[i] = row;
            __threadfence();
        }
        __syncthreads();

        if (tid == 0) {
            unsigned old = atomicAdd(&g_ctr, 1u);
            s_last = (old == 31u);
        }
        __syncthreads();
        if (!s_last) return;

        // last block: deterministic final reduce over 512 rows
        double* sp = (double*)pool;         // 512 doubles
        double* sa = (double*)pool + 512;   // 512 doubles
        __syncthreads();
        sp[tid] = g_pos_row[tid];
        sa[tid] = g_all_row[tid];
        __syncthreads();
        #pragma unroll
        for (int s = 256; s > 0; s >>= 1) {
            if (tid < s) { sp[tid] += sp[tid + s]; sa[tid] += sa[tid + s]; }
            __syncthreads();
        }
        if (tid == 0) {
            out[0] = (float)(sp[0] / 512.0 - sa[0] / (512.0 * 512.0));
            g_ctr = 0;  // reset for next graph replay
        }
        for (int k = tid + 1; k < out_size; k += 512) out[k] = 0.0f;
    }
}

// ---------------------------------------------------------------------------
extern "C" void kernel_launch(void* const* d_in, const int* in_sizes, int n_in,
                              void* d_out, int out_size)
{
    const float* x   = (const float*)d_in[0];
    const float* y   = (const float*)d_in[1];
    const float* w1m = (const float*)d_in[2];
    const float* b1m = (const float*)d_in[3];
    const float* w2m = (const float*)d_in[4];
    const float* b2m = (const float*)d_in[5];
    const float* w1l = (const float*)d_in[6];
    const float* b1l = (const float*)d_in[7];
    const float* w2l = (const float*)d_in[8];
    const float* b2l = (const float*)d_in[9];

    k_fused<<<GRID, 512>>>(x, y, w1m, b1m, w2m, b2m, w1l, b1l, w2l, b2l,
                           (float*)d_out, out_size);
}

// round 13
// speedup vs baseline: 1.1616x; 1.1616x over previous
#include <cuda_runtime.h>
#include <cuda_fp16.h>
#include <math.h>
#include <stdint.h>

#define B_  512
#define XD  768
#define YD  128
#define H2_ 512
#define NPART 16
#define KS1 4          // gemm1 K-split (768/4 = 192)
#define KS2 8          // gemm2 K-split (512/8 = 64)

__device__ float  g_H[2][KS1][B_ * H2_];   // gemm1 raw partials
__device__ float  g_Q[2][KS2][B_ * YD];    // gemm2 raw partials
__device__ double g_SyP [NPART][YD];
__device__ double g_Sy2P[NPART][YD];
__device__ double g_pos_row[B_];
__device__ double g_all_row[B_];
__device__ unsigned g_ctr = 0;

// ---------------- fp16 2-term split (Markidis): x = h + l ----------------
__device__ __forceinline__ void split_pack(float x0, float x1,
                                           uint32_t &hi, uint32_t &lo) {
    __half h0 = __float2half_rn(x0), h1 = __float2half_rn(x1);
    float r0 = x0 - __half2float(h0), r1 = x1 - __half2float(h1);
    __half l0 = __float2half_rn(r0), l1 = __float2half_rn(r1);
    __half2 H = __halves2half2(h0, h1), L = __halves2half2(l0, l1);
    hi = *(uint32_t*)&H; lo = *(uint32_t*)&L;
}

#define MMA16(c, A, B) \
    asm volatile("mma.sync.aligned.m16n8k16.row.col.f32.f16.f16.f32 " \
        "{%0,%1,%2,%3},{%4,%5,%6,%7},{%8,%9},{%0,%1,%2,%3};" \
        : "+f"((c)[0]), "+f"((c)[1]), "+f"((c)[2]), "+f"((c)[3]) \
        : "r"((A)[0]), "r"((A)[1]), "r"((A)[2]), "r"((A)[3]), \
          "r"((B)[0]), "r"((B)[1]))

// ---------------------------------------------------------------------------
// Kernel A: blocks 0..127 = GEMM1 partials via 3x-fp16 HMMA m16n8k16,
// slot-contiguous fragment staging (LDS.128/LDS.64 on the compute side).
// blocks 128..143 = y column stats.
// Block: 128x128 tile, K=192 slice, 12 chunks of k16, 512 thr, 16 warps
// (4M x 4N, warp tile 32x32). Double-buffered, one sync per chunk.
// ---------------------------------------------------------------------------
__global__ __launch_bounds__(512) void k_gemm1_mma(
    const float* __restrict__ X, const float* __restrict__ Y,
    const float* __restrict__ Wmu, const float* __restrict__ Wlv)
{
    const int b = blockIdx.x;
    if (b >= 128) {
        const int p = b - 128;
        const int d = threadIdx.x;
        if (d < YD) {
            const int j0 = p * (B_ / NPART);
            double sy0 = 0, sy1 = 0, s20 = 0, s21 = 0;
            #pragma unroll 4
            for (int j = j0; j < j0 + B_ / NPART; j += 2) {
                double v0 = (double)Y[j * YD + d], v1 = (double)Y[(j + 1) * YD + d];
                sy0 += v0; s20 = fma(v0, v0, s20);
                sy1 += v1; s21 = fma(v1, v1, s21);
            }
            g_SyP[p][d] = sy0 + sy1; g_Sy2P[p][d] = s20 + s21;
        }
        return;
    }

    // Ah/Al: [2buf][8mt][32lane][4slot]; Bh/Bl: [2buf][16nt][32lane][2slot]
    __shared__ __align__(16) uint32_t Ah[4096], Al[4096];  // 16KB each pair half
    __shared__ __align__(16) uint32_t Bh[2048], Bl[2048];

    const int head = b & 1;
    const int ks   = (b >> 1) & 3;
    const int t4   = b >> 3;
    const int m0   = (t4 >> 2) * 128;
    const int n0   = (t4 & 3) * 128;
    const int kb   = ks * 192;
    const float* W = head ? Wlv : Wmu;
    float* P       = &g_H[head][ks][0];

    const int tid  = threadIdx.x;
    const int wid  = tid >> 5,  lane = tid & 31;
    const int wm   = wid >> 2,  wn   = wid & 3;
    const int lg   = lane >> 2, lt   = lane & 3;

    // A loader: ar = tid>>2 (row 0..127), akq = tid&3
    const int ar = tid >> 2, akq = tid & 3;
    const int a_mt   = ar >> 4;
    const int a_slot = ((ar >> 3) & 1) + 2 * (akq >> 1);
    const int a_lane = 4 * (ar & 7) + 2 * (akq & 1);
    const float* Xp = X + (size_t)(m0 + ar) * XD + kb + akq * 4;
    // B loader: bkp = tid>>6 (k-pair 0..7), bn2 = tid&63 (n-pair)
    const int bkp = tid >> 6, bn2 = tid & 63;
    const int b_lt = bkp & 3, b_slot = bkp >> 2;
    const float* Wp = W + (size_t)(kb + 2 * bkp) * H2_ + n0 + 2 * bn2;

    float acc[2][4][4] = {};
    float4 xa; float2 w0, w1;

    #define G1_LOAD(ch) do { \
        xa = *(const float4*)(Xp + (ch) * 16); \
        w0 = *(const float2*)(Wp + (size_t)(ch) * 16 * H2_); \
        w1 = *(const float2*)(Wp + (size_t)(ch) * 16 * H2_ + H2_); \
    } while (0)

    #define G1_STAGE(bf) do { \
        uint32_t h01, l01, h23, l23; \
        split_pack(xa.x, xa.y, h01, l01); \
        split_pack(xa.z, xa.w, h23, l23); \
        int ai = (((bf) * 8 + a_mt) * 32 + a_lane) * 4 + a_slot; \
        Ah[ai] = h01; Ah[ai + 4] = h23; \
        Al[ai] = l01; Al[ai + 4] = l23; \
        _Pragma("unroll") \
        for (int j = 0; j < 2; j++) { \
            int n = 2 * bn2 + j; \
            int nt = n >> 3; \
            int pl = (4 * (n & 7) + b_lt) ^ (2 * (nt & 7)); \
            float vk0 = j ? w0.y : w0.x; \
            float vk1 = j ? w1.y : w1.x; \
            uint32_t bhv, blv; \
            split_pack(vk0, vk1, bhv, blv); \
            int bi = (((bf) * 16 + nt) * 32 + pl) * 2 + b_slot; \
            Bh[bi] = bhv; Bl[bi] = blv; \
        } \
    } while (0)

    G1_LOAD(0);
    G1_STAGE(0);
    G1_LOAD(1);
    __syncthreads();

    for (int ch = 0; ch < 12; ch++) {
        const int bfc = ch & 1;
        if (ch + 1 < 12) G1_STAGE((ch + 1) & 1);
        if (ch + 2 < 12) G1_LOAD(ch + 2);

        uint32_t Af[2][4], Afl[2][4];
        #pragma unroll
        for (int mf = 0; mf < 2; mf++) {
            int mt = wm * 2 + mf;
            int ab = ((bfc * 8 + mt) * 32 + lane) * 4;
            uint4 h = *(const uint4*)&Ah[ab];
            uint4 l = *(const uint4*)&Al[ab];
            Af [mf][0] = h.x; Af [mf][1] = h.y; Af [mf][2] = h.z; Af [mf][3] = h.w;
            Afl[mf][0] = l.x; Afl[mf][1] = l.y; Afl[mf][2] = l.z; Afl[mf][3] = l.w;
        }
        uint32_t Bf[4][2], Bfl[4][2];
        #pragma unroll
        for (int nf = 0; nf < 4; nf++) {
            int nt = wn * 4 + nf;
            int bb = ((bfc * 16 + nt) * 32 + (lane ^ (2 * (nt & 7)))) * 2;
            uint2 h = *(const uint2*)&Bh[bb];
            uint2 l = *(const uint2*)&Bl[bb];
            Bf [nf][0] = h.x; Bf [nf][1] = h.y;
            Bfl[nf][0] = l.x; Bfl[nf][1] = l.y;
        }
        #pragma unroll
        for (int mf = 0; mf < 2; mf++)
            #pragma unroll
            for (int nf = 0; nf < 4; nf++) {
                MMA16(acc[mf][nf], Af[mf],  Bf[nf]);
                MMA16(acc[mf][nf], Af[mf],  Bfl[nf]);
                MMA16(acc[mf][nf], Afl[mf], Bf[nf]);
            }
        __syncthreads();
    }

    #pragma unroll
    for (int mf = 0; mf < 2; mf++) {
        int row0 = m0 + wm * 32 + mf * 16 + lg;
        #pragma unroll
        for (int nf = 0; nf < 4; nf++) {
            int col = n0 + wn * 32 + nf * 8 + lt * 2;
            *(float2*)(P + (size_t)row0 * H2_ + col)       = make_float2(acc[mf][nf][0], acc[mf][nf][1]);
            *(float2*)(P + (size_t)(row0 + 8) * H2_ + col) = make_float2(acc[mf][nf][2], acc[mf][nf][3]);
        }
    }
}

// ---------------------------------------------------------------------------
// GEMM2 via 3x-fp16 HMMA, vectorized staging: Q = relu(sum H_j + b1) @ W2.
// Block: 128x128 tile, 512 thr, 16 warps, K=64 slice (4 chunks of k16).
// grid 64 = 2 heads x 4 M x 8 K.
// ---------------------------------------------------------------------------
__global__ __launch_bounds__(512) void k_gemm2_mma(
    const float* __restrict__ b1mu, const float* __restrict__ b1lv,
    const float* __restrict__ W2mu, const float* __restrict__ W2lv)
{
    __shared__ __align__(16) uint32_t Ah[4096], Al[4096];
    __shared__ __align__(16) uint32_t Bh[2048], Bl[2048];

    const int b    = blockIdx.x;
    const int head = b & 1;
    const int ks   = (b >> 1) & 7;
    const int m0   = (b >> 4) * 128;
    const int kb   = ks * 64;
    const float* Hb = &g_H[head][0][0];
    const float* b1 = head ? b1lv : b1mu;
    const float* W  = head ? W2lv : W2mu;
    float*       Q  = g_Q[head][ks];
    const size_t HS = (size_t)B_ * H2_;

    const int tid  = threadIdx.x;
    const int wid  = tid >> 5,  lane = tid & 31;
    const int wm   = wid >> 2,  wn   = wid & 3;
    const int lg   = lane >> 2, lt   = lane & 3;

    const int ar = tid >> 2, akq = tid & 3;
    const int a_mt   = ar >> 4;
    const int a_slot = ((ar >> 3) & 1) + 2 * (akq >> 1);
    const int a_lane = 4 * (ar & 7) + 2 * (akq & 1);
    const size_t aoff = (size_t)(m0 + ar) * H2_ + kb + akq * 4;
    const int bkp = tid >> 6, bn2 = tid & 63;
    const int b_lt = bkp & 3, b_slot = bkp >> 3 == 0 ? bkp >> 2 : bkp >> 2;  // bkp>>2 in {0,1}
    const float* Wp = W + (size_t)(kb + 2 * bkp) * YD + 2 * bn2;

    float acc[2][4][4] = {};
    float4 hh0, hh1, hh2, hh3, bv4; float2 w0, w1;

    #define G2_LOAD(ch) do { \
        hh0 = *(const float4*)(Hb + 0 * HS + aoff + (ch) * 16); \
        hh1 = *(const float4*)(Hb + 1 * HS + aoff + (ch) * 16); \
        hh2 = *(const float4*)(Hb + 2 * HS + aoff + (ch) * 16); \
        hh3 = *(const float4*)(Hb + 3 * HS + aoff + (ch) * 16); \
        bv4 = *(const float4*)(b1 + kb + akq * 4 + (ch) * 16); \
        w0  = *(const float2*)(Wp + (size_t)(ch) * 16 * YD); \
        w1  = *(const float2*)(Wp + (size_t)(ch) * 16 * YD + YD); \
    } while (0)

    #define G2_STAGE(bf) do { \
        float e0 = fmaxf(hh0.x + hh1.x + hh2.x + hh3.x + bv4.x, 0.0f); \
        float e1 = fmaxf(hh0.y + hh1.y + hh2.y + hh3.y + bv4.y, 0.0f); \
        float e2 = fmaxf(hh0.z + hh1.z + hh2.z + hh3.z + bv4.z, 0.0f); \
        float e3 = fmaxf(hh0.w + hh1.w + hh2.w + hh3.w + bv4.w, 0.0f); \
        uint32_t h01, l01, h23, l23; \
        split_pack(e0, e1, h01, l01); \
        split_pack(e2, e3, h23, l23); \
        int ai = (((bf) * 8 + a_mt) * 32 + a_lane) * 4 + a_slot; \
        Ah[ai] = h01; Ah[ai + 4] = h23; \
        Al[ai] = l01; Al[ai + 4] = l23; \
        _Pragma("unroll") \
        for (int j = 0; j < 2; j++) { \
            int n = 2 * bn2 + j; \
            int nt = n >> 3; \
            int pl = (4 * (n & 7) + b_lt) ^ (2 * (nt & 7)); \
            float vk0 = j ? w0.y : w0.x; \
            float vk1 = j ? w1.y : w1.x; \
            uint32_t bhv, blv; \
            split_pack(vk0, vk1, bhv, blv); \
            int bi = (((bf) * 16 + nt) * 32 + pl) * 2 + b_slot; \
            Bh[bi] = bhv; Bl[bi] = blv; \
        } \
    } while (0)

    G2_LOAD(0);
    G2_STAGE(0);
    G2_LOAD(1);
    __syncthreads();

    for (int ch = 0; ch < 4; ch++) {
        const int bfc = ch & 1;
        if (ch + 1 < 4) G2_STAGE((ch + 1) & 1);
        if (ch + 2 < 4) G2_LOAD(ch + 2);

        uint32_t Af[2][4], Afl[2][4];
        #pragma unroll
        for (int mf = 0; mf < 2; mf++) {
            int mt = wm * 2 + mf;
            int ab = ((bfc * 8 + mt) * 32 + lane) * 4;
            uint4 h = *(const uint4*)&Ah[ab];
            uint4 l = *(const uint4*)&Al[ab];
            Af [mf][0] = h.x; Af [mf][1] = h.y; Af [mf][2] = h.z; Af [mf][3] = h.w;
            Afl[mf][0] = l.x; Afl[mf][1] = l.y; Afl[mf][2] = l.z; Afl[mf][3] = l.w;
        }
        uint32_t Bf[4][2], Bfl[4][2];
        #pragma unroll
        for (int nf = 0; nf < 4; nf++) {
            int nt = wn * 4 + nf;
            int bb = ((bfc * 16 + nt) * 32 + (lane ^ (2 * (nt & 7)))) * 2;
            uint2 h = *(const uint2*)&Bh[bb];
            uint2 l = *(const uint2*)&Bl[bb];
            Bf [nf][0] = h.x; Bf [nf][1] = h.y;
            Bfl[nf][0] = l.x; Bfl[nf][1] = l.y;
        }
        #pragma unroll
        for (int mf = 0; mf < 2; mf++)
            #pragma unroll
            for (int nf = 0; nf < 4; nf++) {
                MMA16(acc[mf][nf], Af[mf],  Bf[nf]);
                MMA16(acc[mf][nf], Af[mf],  Bfl[nf]);
                MMA16(acc[mf][nf], Afl[mf], Bf[nf]);
            }
        __syncthreads();
    }

    #pragma unroll
    for (int mf = 0; mf < 2; mf++) {
        int row0 = m0 + wm * 32 + mf * 16 + lg;
        #pragma unroll
        for (int nf = 0; nf < 4; nf++) {
            int col = wn * 32 + nf * 8 + lt * 2;
            *(float2*)(Q + (size_t)row0 * YD + col)       = make_float2(acc[mf][nf][0], acc[mf][nf][1]);
            *(float2*)(Q + (size_t)(row0 + 8) * YD + col) = make_float2(acc[mf][nf][2], acc[mf][nf][3]);
        }
    }
}

// ---------------------------------------------------------------------------
// Kernel C: epilogue + per-row reductions + final scalar (last-block ticket).
// negative == all_probs exactly in fp32 (511 + e^-20 == 511; log(B-1) cancels)
// ---------------------------------------------------------------------------
__global__ __launch_bounds__(128) void k_rows_final(
    const float* __restrict__ Y,
    const float* __restrict__ b2mu, const float* __restrict__ b2lv,
    float* __restrict__ out, int out_size)
{
    __shared__ double sSy[YD];
    __shared__ double sSy2[YD];
    __shared__ bool s_last;

    const int tid = threadIdx.x;
    {
        double s = 0.0, s2 = 0.0;
        #pragma unroll
        for (int p = 0; p < NPART; p++) { s += g_SyP[p][tid]; s2 += g_Sy2P[p][tid]; }
        sSy[tid] = s; sSy2[tid] = s2;
    }
    __syncthreads();

    const int lane = tid & 31;
    const int wid  = tid >> 5;
    const int i    = blockIdx.x * 4 + wid;

    double pos = 0.0, row = 0.0;
    #pragma unroll
    for (int q = 0; q < 4; q++) {
        int d = q * 32 + lane;
        int idx = i * YD + d;
        float muf = b2mu[d];
        float sf  = b2lv[d];
        #pragma unroll
        for (int j = 0; j < KS2; j++) {
            muf += g_Q[0][j][idx];
            sf  += g_Q[1][j][idx];
        }
        float lvf = tanhf(sf);
        float ivf = expf(-lvf);
        float yf  = Y[idx];

        float dmy = muf - yf;
        pos += (double)fmaf(-0.5f * dmy * dmy, ivf, -0.5f * lvf);

        double mu = (double)muf;
        double tq = fma(mu, fma(512.0, mu, -2.0 * sSy[d]), sSy2[d]);
        row = fma(-0.5 * (double)ivf, tq, row);
        row = fma(-256.0, (double)lvf, row);
    }
    #pragma unroll
    for (int off = 16; off > 0; off >>= 1) {
        pos += __shfl_down_sync(0xffffffffu, pos, off);
        row += __shfl_down_sync(0xffffffffu, row, off);
    }
    if (lane == 0) {
        g_pos_row[i] = pos;
        g_all_row[i] = row;
        __threadfence();
    }
    __syncthreads();

    if (tid == 0) {
        unsigned old = atomicAdd(&g_ctr, 1u);
        s_last = (old == gridDim.x - 1);
    }
    __syncthreads();
    if (!s_last) return;

    double p0 = 0.0, a0 = 0.0;
    #pragma unroll
    for (int j = tid; j < B_; j += 128) { p0 += g_pos_row[j]; a0 += g_all_row[j]; }
    sSy[tid]  = p0;
    sSy2[tid] = a0;
    __syncthreads();
    #pragma unroll
    for (int s = 64; s > 0; s >>= 1) {
        if (tid < s) { sSy[tid] += sSy[tid + s]; sSy2[tid] += sSy2[tid + s]; }
        __syncthreads();
    }
    if (tid == 0) {
        out[0] = (float)(sSy[0] / 512.0 - sSy2[0] / (512.0 * 512.0));
        g_ctr = 0;
    }
    for (int k = tid + 1; k < out_size; k += 128) out[k] = 0.0f;
}

// ---------------------------------------------------------------------------
extern "C" void kernel_launch(void* const* d_in, const int* in_sizes, int n_in,
                              void* d_out, int out_size)
{
    const float* x   = (const float*)d_in[0];
    const float* y   = (const float*)d_in[1];
    const float* w1m = (const float*)d_in[2];
    const float* b1m = (const float*)d_in[3];
    const float* w2m = (const float*)d_in[4];
    const float* b2m = (const float*)d_in[5];
    const float* w1l = (const float*)d_in[6];
    const float* b1l = (const float*)d_in[7];
    const float* w2l = (const float*)d_in[8];
    const float* b2l = (const float*)d_in[9];

    k_gemm1_mma<<<128 + NPART, 512>>>(x, y, w1m, w1l);
    k_gemm2_mma<<<64, 512>>>(b1m, b1l, w2m, w2l);
    k_rows_final<<<B_ / 4, 128>>>(y, b2m, b2l, (float*)d_out, out_size);
}

// round 14
// speedup vs baseline: 1.1705x; 1.0077x over previous
#include <cuda_runtime.h>
#include <cuda_fp16.h>
#include <math.h>
#include <stdint.h>

#define B_  512
#define XD  768
#define YD  128
#define H2_ 512
#define NPART 16
#define KS1 4          // gemm1 K-split (768/4 = 192)
#define KS2 8          // gemm2 K-split (512/8 = 64)
#define APITCH 33

__device__ float  g_H[2][KS1][B_ * H2_];   // gemm1 raw partials
__device__ float  g_Q[2][KS2][B_ * YD];    // gemm2 raw partials
__device__ double g_SyP [NPART][YD];
__device__ double g_Sy2P[NPART][YD];
__device__ double g_pos_row[B_];
__device__ double g_all_row[B_];
__device__ unsigned g_ctr = 0;

// pre-converted hi/lo half2-packed operands (pairs along K)
__device__ uint32_t g_Xh [B_ * XD / 2],  g_Xl [B_ * XD / 2];        // [r][kp]
__device__ uint32_t g_W1h[2][(XD/2) * H2_], g_W1l[2][(XD/2) * H2_]; // [kp][n]
__device__ uint32_t g_W2h[2][(H2_/2) * YD], g_W2l[2][(H2_/2) * YD]; // [kp][n]

// ---------------- fp16 2-term split (Markidis): x = h + l ----------------
__device__ __forceinline__ void split_pack(float x0, float x1,
                                           uint32_t &hi, uint32_t &lo) {
    __half h0 = __float2half_rn(x0), h1 = __float2half_rn(x1);
    float r0 = x0 - __half2float(h0), r1 = x1 - __half2float(h1);
    __half l0 = __float2half_rn(r0), l1 = __float2half_rn(r1);
    __half2 H = __halves2half2(h0, h1), L = __halves2half2(l0, l1);
    hi = *(uint32_t*)&H; lo = *(uint32_t*)&L;
}

#define MMA16(c, A, B) \
    asm volatile("mma.sync.aligned.m16n8k16.row.col.f32.f16.f16.f32 " \
        "{%0,%1,%2,%3},{%4,%5,%6,%7},{%8,%9},{%0,%1,%2,%3};" \
        : "+f"((c)[0]), "+f"((c)[1]), "+f"((c)[2]), "+f"((c)[3]) \
        : "r"((A)[0]), "r"((A)[1]), "r"((A)[2]), "r"((A)[3]), \
          "r"((B)[0]), "r"((B)[1]))

// ---------------------------------------------------------------------------
// Kernel 0: pre-convert X, W1, W2 into hi/lo half2 pair arrays + y stats.
// blocks 0..47: X  (196608 pairs)   [r][kp] = (X[r][2kp], X[r][2kp+1])
// blocks 48..143: W1 (2 heads)      [kp][n] = (W[2kp][n], W[2kp+1][n])
// blocks 144..159: W2 (2 heads)     same pairing
// blocks 160..175: y column stats
// ---------------------------------------------------------------------------
__global__ __launch_bounds__(256) void k_pre(
    const float* __restrict__ X,   const float* __restrict__ Y,
    const float* __restrict__ w1m, const float* __restrict__ w1lv,
    const float* __restrict__ w2m, const float* __restrict__ w2lv)
{
    const int b = blockIdx.x, tid = threadIdx.x;

    if (b >= 160) {
        const int p = b - 160;
        const int d = tid;
        if (d < YD) {
            const int j0 = p * (B_ / NPART);
            double sy0 = 0, sy1 = 0, s20 = 0, s21 = 0;
            #pragma unroll 4
            for (int j = j0; j < j0 + B_ / NPART; j += 2) {
                double v0 = (double)Y[j * YD + d], v1 = (double)Y[(j + 1) * YD + d];
                sy0 += v0; s20 = fma(v0, v0, s20);
                sy1 += v1; s21 = fma(v1, v1, s21);
            }
            g_SyP[p][d] = sy0 + sy1; g_Sy2P[p][d] = s20 + s21;
        }
        return;
    }

    if (b < 48) {
        const int t = b * 256 + tid;           // 0..12287
        #pragma unroll 4
        for (int i = 0; i < 16; i++) {
            int p = t + i * 12288;             // pair index: r*384 + kp
            float2 v = *(const float2*)(X + 2 * (size_t)p);
            split_pack(v.x, v.y, g_Xh[p], g_Xl[p]);
        }
    } else if (b < 144) {
        const int seg = (b - 48) / 48;         // 0 = mu, 1 = lv
        const float* W = seg ? w1lv : w1m;
        uint32_t* oh = g_W1h[seg];
        uint32_t* ol = g_W1l[seg];
        const int t = ((b - 48) % 48) * 256 + tid;
        #pragma unroll 4
        for (int i = 0; i < 16; i++) {
            int p = t + i * 12288;             // kp*512 + n
            int kp = p >> 9, n = p & 511;
            float v0 = W[(size_t)(2 * kp) * H2_ + n];
            float v1 = W[(size_t)(2 * kp + 1) * H2_ + n];
            split_pack(v0, v1, oh[p], ol[p]);
        }
    } else {
        const int seg = (b - 144) / 8;
        const float* W = seg ? w2lv : w2m;
        uint32_t* oh = g_W2h[seg];
        uint32_t* ol = g_W2l[seg];
        const int t = ((b - 144) % 8) * 256 + tid;
        #pragma unroll 4
        for (int i = 0; i < 16; i++) {
            int p = t + i * 2048;              // kp*128 + n
            int kp = p >> 7, n = p & 127;
            float v0 = W[(size_t)(2 * kp) * YD + n];
            float v1 = W[(size_t)(2 * kp + 1) * YD + n];
            split_pack(v0, v1, oh[p], ol[p]);
        }
    }
}

// ---------------------------------------------------------------------------
// Kernel A (= R11 gemm1, staging from pre-converted arrays, no cvt in loop):
// 128 blocks, 128x128 tile, K=192 slice, 12 chunks of k16, 512 thr, 16 warps
// (4M x 4N, warp tile 32x32). Double-buffered, one sync per chunk.
// ---------------------------------------------------------------------------
__global__ __launch_bounds__(512) void k_gemm1_mma()
{
    __shared__ uint32_t Ah[2 * 8 * 4 * APITCH], Al[2 * 8 * 4 * APITCH];
    __shared__ uint32_t Bh[2 * 16 * 2 * APITCH], Bl[2 * 16 * 2 * APITCH];

    const int b = blockIdx.x;
    const int head = b & 1;
    const int ks   = (b >> 1) & 3;
    const int t4   = b >> 3;
    const int m0   = (t4 >> 2) * 128;
    const int n0   = (t4 & 3) * 128;
    const int kb   = ks * 192;
    float* P       = &g_H[head][ks][0];

    const int tid  = threadIdx.x;
    const int wid  = tid >> 5,  lane = tid & 31;
    const int wm   = wid >> 2,  wn   = wid & 3;
    const int lg   = lane >> 2, lt   = lane & 3;

    // A loader: ar = tid>>2 (row 0..127), akq = tid&3 (k-quad)
    const int ar = tid >> 2, akq = tid & 3;
    const int a_mt   = ar >> 4;
    const int a_slot = ((ar >> 3) & 1) + 2 * (akq >> 1);
    const int a_lane = 4 * (ar & 7) + 2 * (akq & 1);
    const uint32_t* Xhp = g_Xh + (size_t)(m0 + ar) * (XD / 2) + (kb >> 1) + akq * 2;
    const uint32_t* Xlp = g_Xl + (size_t)(m0 + ar) * (XD / 2) + (kb >> 1) + akq * 2;
    // B loader: bkp = tid>>6 (k-pair 0..7), bn2 = tid&63 (n-pair)
    const int bkp = tid >> 6, bn2 = tid & 63;
    const int b_lt = bkp & 3, b_slot = bkp >> 2;
    const uint32_t* Bhp = g_W1h[head] + (size_t)((kb >> 1) + bkp) * H2_ + n0 + 2 * bn2;
    const uint32_t* Blp = g_W1l[head] + (size_t)((kb >> 1) + bkp) * H2_ + n0 + 2 * bn2;

    float acc[2][4][4] = {};
    uint2 axh, axl, bxh, bxl;

    #define G1_LOAD(ch) do { \
        axh = *(const uint2*)(Xhp + (ch) * 8); \
        axl = *(const uint2*)(Xlp + (ch) * 8); \
        bxh = *(const uint2*)(Bhp + (size_t)(ch) * 8 * H2_); \
        bxl = *(const uint2*)(Blp + (size_t)(ch) * 8 * H2_); \
    } while (0)

    #define G1_STAGE(bf) do { \
        int ai = (((bf) * 8 + a_mt) * 4 + a_slot) * APITCH + a_lane; \
        Ah[ai] = axh.x; Ah[ai + 1] = axh.y; \
        Al[ai] = axl.x; Al[ai + 1] = axl.y; \
        _Pragma("unroll") \
        for (int j = 0; j < 2; j++) { \
            int n = 2 * bn2 + j; \
            int nt = n >> 3; \
            int bi = (((bf) * 16 + nt) * 2 + b_slot) * APITCH + 4 * (n & 7) + b_lt; \
            Bh[bi] = j ? bxh.y : bxh.x; \
            Bl[bi] = j ? bxl.y : bxl.x; \
        } \
    } while (0)

    G1_LOAD(0);
    G1_STAGE(0);
    G1_LOAD(1);
    __syncthreads();

    for (int ch = 0; ch < 12; ch++) {
        const int bfc = ch & 1;
        if (ch + 1 < 12) G1_STAGE((ch + 1) & 1);
        if (ch + 2 < 12) G1_LOAD(ch + 2);

        uint32_t Af[2][4], Afl[2][4];
        #pragma unroll
        for (int mf = 0; mf < 2; mf++) {
            int mt = wm * 2 + mf;
            int base = ((bfc * 8 + mt) * 4) * APITCH + lane;
            #pragma unroll
            for (int s = 0; s < 4; s++) {
                Af [mf][s] = Ah[base + s * APITCH];
                Afl[mf][s] = Al[base + s * APITCH];
            }
        }
        uint32_t Bf[4][2], Bfl[4][2];
        #pragma unroll
        for (int nf = 0; nf < 4; nf++) {
            int nt = wn * 4 + nf;
            int base = ((bfc * 16 + nt) * 2) * APITCH + lane;
            #pragma unroll
            for (int s = 0; s < 2; s++) {
                Bf [nf][s] = Bh[base + s * APITCH];
                Bfl[nf][s] = Bl[base + s * APITCH];
            }
        }
        #pragma unroll
        for (int mf = 0; mf < 2; mf++)
            #pragma unroll
            for (int nf = 0; nf < 4; nf++) {
                MMA16(acc[mf][nf], Af[mf],  Bf[nf]);
                MMA16(acc[mf][nf], Af[mf],  Bfl[nf]);
                MMA16(acc[mf][nf], Afl[mf], Bf[nf]);
            }
        __syncthreads();
    }

    #pragma unroll
    for (int mf = 0; mf < 2; mf++) {
        int row0 = m0 + wm * 32 + mf * 16 + lg;
        #pragma unroll
        for (int nf = 0; nf < 4; nf++) {
            int col = n0 + wn * 32 + nf * 8 + lt * 2;
            *(float2*)(P + (size_t)row0 * H2_ + col)       = make_float2(acc[mf][nf][0], acc[mf][nf][1]);
            *(float2*)(P + (size_t)(row0 + 8) * H2_ + col) = make_float2(acc[mf][nf][2], acc[mf][nf][3]);
        }
    }
}

// ---------------------------------------------------------------------------
// Kernel B (= R11 gemm2, W2 pre-converted; A live from g_H sums):
// Block: 64x128 tile, K=64 slice (4 chunks of k16), 256 thr, 8 warps
// (2M x 4N, warp tile 32x32), double-buffered. grid 128 = 2 x 8 M x 8 K.
// ---------------------------------------------------------------------------
__global__ __launch_bounds__(256) void k_gemm2_mma(
    const float* __restrict__ b1mu, const float* __restrict__ b1lv)
{
    __shared__ uint32_t Ah[2 * 4 * 4 * APITCH], Al[2 * 4 * 4 * APITCH];
    __shared__ uint32_t Bh[2 * 16 * 2 * APITCH], Bl[2 * 16 * 2 * APITCH];

    const int b    = blockIdx.x;
    const int head = b & 1;
    const int ks   = (b >> 1) & 7;
    const int m0   = (b >> 4) * 64;
    const int kb   = ks * 64;
    const float* Hb = &g_H[head][0][0];
    const float* b1 = head ? b1lv : b1mu;
    float*       Q  = g_Q[head][ks];
    const size_t HS = (size_t)B_ * H2_;

    const int tid  = threadIdx.x;
    const int wid  = tid >> 5,  lane = tid & 31;
    const int wm   = wid >> 2,  wn   = wid & 3;
    const int lg   = lane >> 2, lt   = lane & 3;

    // A loader: ar = tid>>2 (0..63), akq = tid&3
    const int ar = tid >> 2, akq = tid & 3;
    const int a_mt   = ar >> 4;            // 0..3
    const int a_slot = ((ar >> 3) & 1) + 2 * (akq >> 1);
    const int a_lane = 4 * (ar & 7) + 2 * (akq & 1);
    const size_t aoff = (size_t)(m0 + ar) * H2_ + kb + akq * 4;
    // B loader: bkp = tid>>5 (0..7), bn2b = tid&31 (2 n-pair units)
    const int bkp = tid >> 5, bn2b = tid & 31;
    const int b_lt = bkp & 3, b_slot = bkp >> 2;
    const uint32_t* Bhp = g_W2h[head] + (size_t)((kb >> 1) + bkp) * YD;
    const uint32_t* Blp = g_W2l[head] + (size_t)((kb >> 1) + bkp) * YD;

    float acc[2][4][4] = {};
    float4 hh0, hh1, hh2, hh3, bv4;
    uint2 wh[2], wl[2];

    #define G2_LOAD(ch) do { \
        hh0 = *(const float4*)(Hb + 0 * HS + aoff + (ch) * 16); \
        hh1 = *(const float4*)(Hb + 1 * HS + aoff + (ch) * 16); \
        hh2 = *(const float4*)(Hb + 2 * HS + aoff + (ch) * 16); \
        hh3 = *(const float4*)(Hb + 3 * HS + aoff + (ch) * 16); \
        bv4 = *(const float4*)(b1 + kb + akq * 4 + (ch) * 16); \
        _Pragma("unroll") \
        for (int u = 0; u < 2; u++) { \
            wh[u] = *(const uint2*)(Bhp + (size_t)(ch) * 8 * YD + 2 * (bn2b + 32 * u)); \
            wl[u] = *(const uint2*)(Blp + (size_t)(ch) * 8 * YD + 2 * (bn2b + 32 * u)); \
        } \
    } while (0)

    #define G2_STAGE(bf) do { \
        float e0 = fmaxf(hh0.x + hh1.x + hh2.x + hh3.x + bv4.x, 0.0f); \
        float e1 = fmaxf(hh0.y + hh1.y + hh2.y + hh3.y + bv4.y, 0.0f); \
        float e2 = fmaxf(hh0.z + hh1.z + hh2.z + hh3.z + bv4.z, 0.0f); \
        float e3 = fmaxf(hh0.w + hh1.w + hh2.w + hh3.w + bv4.w, 0.0f); \
        uint32_t h01, l01, h23, l23; \
        split_pack(e0, e1, h01, l01); \
        split_pack(e2, e3, h23, l23); \
        int ai = (((bf) * 4 + a_mt) * 4 + a_slot) * APITCH + a_lane; \
        Ah[ai] = h01; Ah[ai + 1] = h23; \
        Al[ai] = l01; Al[ai + 1] = l23; \
        _Pragma("unroll") \
        for (int u = 0; u < 2; u++) { \
            _Pragma("unroll") \
            for (int j = 0; j < 2; j++) { \
                int n = 2 * (bn2b + 32 * u) + j; \
                int nt = n >> 3; \
                int bi = (((bf) * 16 + nt) * 2 + b_slot) * APITCH + 4 * (n & 7) + b_lt; \
                Bh[bi] = j ? wh[u].y : wh[u].x; \
                Bl[bi] = j ? wl[u].y : wl[u].x; \
            } \
        } \
    } while (0)

    G2_LOAD(0);
    G2_STAGE(0);
    G2_LOAD(1);
    __syncthreads();

    for (int ch = 0; ch < 4; ch++) {
        const int bfc = ch & 1;
        if (ch + 1 < 4) G2_STAGE((ch + 1) & 1);
        if (ch + 2 < 4) G2_LOAD(ch + 2);

        uint32_t Af[2][4], Afl[2][4];
        #pragma unroll
        for (int mf = 0; mf < 2; mf++) {
            int mt = wm * 2 + mf;
            int base = ((bfc * 4 + mt) * 4) * APITCH + lane;
            #pragma unroll
            for (int s = 0; s < 4; s++) {
                Af [mf][s] = Ah[base + s * APITCH];
                Afl[mf][s] = Al[base + s * APITCH];
            }
        }
        uint32_t Bf[4][2], Bfl[4][2];
        #pragma unroll
        for (int nf = 0; nf < 4; nf++) {
            int nt = wn * 4 + nf;
            int base = ((bfc * 16 + nt) * 2) * APITCH + lane;
            #pragma unroll
            for (int s = 0; s < 2; s++) {
                Bf [nf][s] = Bh[base + s * APITCH];
                Bfl[nf][s] = Bl[base + s * APITCH];
            }
        }
        #pragma unroll
        for (int mf = 0; mf < 2; mf++)
            #pragma unroll
            for (int nf = 0; nf < 4; nf++) {
                MMA16(acc[mf][nf], Af[mf],  Bf[nf]);
                MMA16(acc[mf][nf], Af[mf],  Bfl[nf]);
                MMA16(acc[mf][nf], Afl[mf], Bf[nf]);
            }
        __syncthreads();
    }

    #pragma unroll
    for (int mf = 0; mf < 2; mf++) {
        int row0 = m0 + wm * 32 + mf * 16 + lg;
        #pragma unroll
        for (int nf = 0; nf < 4; nf++) {
            int col = (wn * 4 + nf) * 8 + lt * 2;
            *(float2*)(Q + (size_t)row0 * YD + col)       = make_float2(acc[mf][nf][0], acc[mf][nf][1]);
            *(float2*)(Q + (size_t)(row0 + 8) * YD + col) = make_float2(acc[mf][nf][2], acc[mf][nf][3]);
        }
    }
}

// ---------------------------------------------------------------------------
// Kernel C: epilogue + per-row reductions + final scalar (last-block ticket).
// negative == all_probs exactly in fp32 (511 + e^-20 == 511; log(B-1) cancels)
// ---------------------------------------------------------------------------
__global__ __launch_bounds__(128) void k_rows_final(
    const float* __restrict__ Y,
    const float* __restrict__ b2mu, const float* __restrict__ b2lv,
    float* __restrict__ out, int out_size)
{
    __shared__ double sSy[YD];
    __shared__ double sSy2[YD];
    __shared__ bool s_last;

    const int tid = threadIdx.x;
    {
        double s = 0.0, s2 = 0.0;
        #pragma unroll
        for (int p = 0; p < NPART; p++) { s += g_SyP[p][tid]; s2 += g_Sy2P[p][tid]; }
        sSy[tid] = s; sSy2[tid] = s2;
    }
    __syncthreads();

    const int lane = tid & 31;
    const int wid  = tid >> 5;
    const int i    = blockIdx.x * 4 + wid;

    double pos = 0.0, row = 0.0;
    #pragma unroll
    for (int q = 0; q < 4; q++) {
        int d = q * 32 + lane;
        int idx = i * YD + d;
        float muf = b2mu[d];
        float sf  = b2lv[d];
        #pragma unroll
        for (int j = 0; j < KS2; j++) {
            muf += g_Q[0][j][idx];
            sf  += g_Q[1][j][idx];
        }
        float lvf = tanhf(sf);
        float ivf = expf(-lvf);
        float yf  = Y[idx];

        float dmy = muf - yf;
        pos += (double)fmaf(-0.5f * dmy * dmy, ivf, -0.5f * lvf);

        double mu = (double)muf;
        double tq = fma(mu, fma(512.0, mu, -2.0 * sSy[d]), sSy2[d]);
        row = fma(-0.5 * (double)ivf, tq, row);
        row = fma(-256.0, (double)lvf, row);
    }
    #pragma unroll
    for (int off = 16; off > 0; off >>= 1) {
        pos += __shfl_down_sync(0xffffffffu, pos, off);
        row += __shfl_down_sync(0xffffffffu, row, off);
    }
    if (lane == 0) {
        g_pos_row[i] = pos;
        g_all_row[i] = row;
        __threadfence();
    }
    __syncthreads();

    if (tid == 0) {
        unsigned old = atomicAdd(&g_ctr, 1u);
        s_last = (old == gridDim.x - 1);
    }
    __syncthreads();
    if (!s_last) return;

    double p0 = 0.0, a0 = 0.0;
    #pragma unroll
    for (int j = tid; j < B_; j += 128) { p0 += g_pos_row[j]; a0 += g_all_row[j]; }
    sSy[tid]  = p0;
    sSy2[tid] = a0;
    __syncthreads();
    #pragma unroll
    for (int s = 64; s > 0; s >>= 1) {
        if (tid < s) { sSy[tid] += sSy[tid + s]; sSy2[tid] += sSy2[tid + s]; }
        __syncthreads();
    }
    if (tid == 0) {
        out[0] = (float)(sSy[0] / 512.0 - sSy2[0] / (512.0 * 512.0));
        g_ctr = 0;
    }
    for (int k = tid + 1; k < out_size; k += 128) out[k] = 0.0f;
}

// ---------------------------------------------------------------------------
extern "C" void kernel_launch(void* const* d_in, const int* in_sizes, int n_in,
                              void* d_out, int out_size)
{
    const float* x   = (const float*)d_in[0];
    const float* y   = (const float*)d_in[1];
    const float* w1m = (const float*)d_in[2];
    const float* b1m = (const float*)d_in[3];
    const float* w2m = (const float*)d_in[4];
    const float* b2m = (const float*)d_in[5];
    const float* w1l = (const float*)d_in[6];
    const float* b1l = (const float*)d_in[7];
    const float* w2l = (const float*)d_in[8];
    const float* b2l = (const float*)d_in[9];

    k_pre<<<176, 256>>>(x, y, w1m, w1l, w2m, w2l);
    k_gemm1_mma<<<128, 512>>>();
    k_gemm2_mma<<<128, 256>>>(b1m, b1l);
    k_rows_final<<<B_ / 4, 128>>>(y, b2m, b2l, (float*)d_out, out_size);
}

// round 15
// speedup vs baseline: 1.2284x; 1.0495x over previous
#include <cuda_runtime.h>
#include <cuda_fp16.h>
#include <math.h>
#include <stdint.h>

#define B_  512
#define XD  768
#define YD  128
#define H2_ 512
#define NPART 16
#define KS1 4          // gemm1 K-split (768/4 = 192)
#define KS2 8          // gemm2 K-split (512/8 = 64)
#define APITCH 33

__device__ float  g_H[2][KS1][B_ * H2_];   // gemm1 raw partials
__device__ float  g_Q[2][KS2][B_ * YD];    // gemm2 raw partials
__device__ double g_SyP [NPART][YD];
__device__ double g_Sy2P[NPART][YD];
__device__ double g_pos_row[B_];
__device__ double g_all_row[B_];
__device__ unsigned g_ctr = 0;

// ---------------- fp16 2-term split (Markidis): x = h + l ----------------
__device__ __forceinline__ void split_pack(float x0, float x1,
                                           uint32_t &hi, uint32_t &lo) {
    __half h0 = __float2half_rn(x0), h1 = __float2half_rn(x1);
    float r0 = x0 - __half2float(h0), r1 = x1 - __half2float(h1);
    __half l0 = __float2half_rn(r0), l1 = __float2half_rn(r1);
    __half2 H = __halves2half2(h0, h1), L = __halves2half2(l0, l1);
    hi = *(uint32_t*)&H; lo = *(uint32_t*)&L;
}

#define MMA16(c, A, B) \
    asm volatile("mma.sync.aligned.m16n8k16.row.col.f32.f16.f16.f32 " \
        "{%0,%1,%2,%3},{%4,%5,%6,%7},{%8,%9},{%0,%1,%2,%3};" \
        : "+f"((c)[0]), "+f"((c)[1]), "+f"((c)[2]), "+f"((c)[3]) \
        : "r"((A)[0]), "r"((A)[1]), "r"((A)[2]), "r"((A)[3]), \
          "r"((B)[0]), "r"((B)[1]))

// ---------------------------------------------------------------------------
// Kernel A (R11-proven): blocks 0..127 = GEMM1 partials via 3x-fp16 HMMA,
// blocks 128..143 = y column stats.
// Block: 128x128 tile, K=192 slice, 12 chunks of k16, 512 thr, 16 warps
// (4M x 4N, warp tile 32x32). Double-buffered, one sync per chunk.
// ---------------------------------------------------------------------------
__global__ __launch_bounds__(512) void k_gemm1_mma(
    const float* __restrict__ X, const float* __restrict__ Y,
    const float* __restrict__ Wmu, const float* __restrict__ Wlv)
{
    const int b = blockIdx.x;
    if (b >= 128) {
        const int p = b - 128;
        const int d = threadIdx.x;
        if (d < YD) {
            const int j0 = p * (B_ / NPART);
            double sy0 = 0, sy1 = 0, s20 = 0, s21 = 0;
            #pragma unroll 4
            for (int j = j0; j < j0 + B_ / NPART; j += 2) {
                double v0 = (double)Y[j * YD + d], v1 = (double)Y[(j + 1) * YD + d];
                sy0 += v0; s20 = fma(v0, v0, s20);
                sy1 += v1; s21 = fma(v1, v1, s21);
            }
            g_SyP[p][d] = sy0 + sy1; g_Sy2P[p][d] = s20 + s21;
        }
        return;
    }

    __shared__ uint32_t Ah[2 * 8 * 4 * APITCH], Al[2 * 8 * 4 * APITCH];
    __shared__ uint32_t Bh[2 * 16 * 2 * APITCH], Bl[2 * 16 * 2 * APITCH];

    const int head = b & 1;
    const int ks   = (b >> 1) & 3;
    const int t4   = b >> 3;
    const int m0   = (t4 >> 2) * 128;
    const int n0   = (t4 & 3) * 128;
    const int kb   = ks * 192;
    const float* W = head ? Wlv : Wmu;
    float* P       = &g_H[head][ks][0];

    const int tid  = threadIdx.x;
    const int wid  = tid >> 5,  lane = tid & 31;
    const int wm   = wid >> 2,  wn   = wid & 3;
    const int lg   = lane >> 2, lt   = lane & 3;

    const int ar = tid >> 2, akq = tid & 3;
    const int a_mt   = ar >> 4;
    const int a_slot = ((ar >> 3) & 1) + 2 * (akq >> 1);
    const int a_lane = 4 * (ar & 7) + 2 * (akq & 1);
    const float* Xp = X + (size_t)(m0 + ar) * XD + kb + akq * 4;
    const int bkp = tid >> 6, bn2 = tid & 63;
    const int b_lt = bkp & 3, b_slot = bkp >> 2;
    const float* Wp = W + (size_t)(kb + 2 * bkp) * H2_ + n0 + 2 * bn2;

    float acc[2][4][4] = {};
    float4 xa; float2 w0, w1;

    #define G1_LOAD(ch) do { \
        xa = *(const float4*)(Xp + (ch) * 16); \
        w0 = *(const float2*)(Wp + (size_t)(ch) * 16 * H2_); \
        w1 = *(const float2*)(Wp + (size_t)(ch) * 16 * H2_ + H2_); \
    } while (0)

    #define G1_STAGE(bf) do { \
        uint32_t h01, l01, h23, l23; \
        split_pack(xa.x, xa.y, h01, l01); \
        split_pack(xa.z, xa.w, h23, l23); \
        int ai = (((bf) * 8 + a_mt) * 4 + a_slot) * APITCH + a_lane; \
        Ah[ai] = h01; Ah[ai + 1] = h23; \
        Al[ai] = l01; Al[ai + 1] = l23; \
        _Pragma("unroll") \
        for (int j = 0; j < 2; j++) { \
            int n = 2 * bn2 + j; \
            int nt = n >> 3; \
            float vk0 = j ? w0.y : w0.x; \
            float vk1 = j ? w1.y : w1.x; \
            uint32_t bhv, blv; \
            split_pack(vk0, vk1, bhv, blv); \
            int bi = (((bf) * 16 + nt) * 2 + b_slot) * APITCH + 4 * (n & 7) + b_lt; \
            Bh[bi] = bhv; Bl[bi] = blv; \
        } \
    } while (0)

    G1_LOAD(0);
    G1_STAGE(0);
    G1_LOAD(1);
    __syncthreads();

    for (int ch = 0; ch < 12; ch++) {
        const int bfc = ch & 1;
        if (ch + 1 < 12) G1_STAGE((ch + 1) & 1);
        if (ch + 2 < 12) G1_LOAD(ch + 2);

        uint32_t Af[2][4], Afl[2][4];
        #pragma unroll
        for (int mf = 0; mf < 2; mf++) {
            int mt = wm * 2 + mf;
            int base = ((bfc * 8 + mt) * 4) * APITCH + lane;
            #pragma unroll
            for (int s = 0; s < 4; s++) {
                Af [mf][s] = Ah[base + s * APITCH];
                Afl[mf][s] = Al[base + s * APITCH];
            }
        }
        uint32_t Bf[4][2], Bfl[4][2];
        #pragma unroll
        for (int nf = 0; nf < 4; nf++) {
            int nt = wn * 4 + nf;
            int base = ((bfc * 16 + nt) * 2) * APITCH + lane;
            #pragma unroll
            for (int s = 0; s < 2; s++) {
                Bf [nf][s] = Bh[base + s * APITCH];
                Bfl[nf][s] = Bl[base + s * APITCH];
            }
        }
        #pragma unroll
        for (int mf = 0; mf < 2; mf++)
            #pragma unroll
            for (int nf = 0; nf < 4; nf++) {
                MMA16(acc[mf][nf], Af[mf],  Bf[nf]);
                MMA16(acc[mf][nf], Af[mf],  Bfl[nf]);
                MMA16(acc[mf][nf], Afl[mf], Bf[nf]);
            }
        __syncthreads();
    }

    #pragma unroll
    for (int mf = 0; mf < 2; mf++) {
        int row0 = m0 + wm * 32 + mf * 16 + lg;
        #pragma unroll
        for (int nf = 0; nf < 4; nf++) {
            int col = n0 + wn * 32 + nf * 8 + lt * 2;
            *(float2*)(P + (size_t)row0 * H2_ + col)       = make_float2(acc[mf][nf][0], acc[mf][nf][1]);
            *(float2*)(P + (size_t)(row0 + 8) * H2_ + col) = make_float2(acc[mf][nf][2], acc[mf][nf][3]);
        }
    }
}

// ---------------------------------------------------------------------------
// GEMM2 (R11-proven): Q[head][ks] = relu(sum_j H_j + b1) @ W2[kslice].
// Block: 64x128 tile, K=64 slice (4 chunks of k16), 256 thr, 8 warps
// (2M x 4N, warp tile 32x32), double-buffered. grid 128 = 2 x 8 M x 8 K.
// ---------------------------------------------------------------------------
__global__ __launch_bounds__(256) void k_gemm2_mma(
    const float* __restrict__ b1mu, const float* __restrict__ b1lv,
    const float* __restrict__ W2mu, const float* __restrict__ W2lv)
{
    __shared__ uint32_t Ah[2 * 4 * 4 * APITCH], Al[2 * 4 * 4 * APITCH];
    __shared__ uint32_t Bh[2 * 16 * 2 * APITCH], Bl[2 * 16 * 2 * APITCH];

    const int b    = blockIdx.x;
    const int head = b & 1;
    const int ks   = (b >> 1) & 7;
    const int m0   = (b >> 4) * 64;
    const int kb   = ks * 64;
    const float* Hb = &g_H[head][0][0];
    const float* b1 = head ? b1lv : b1mu;
    const float* W  = head ? W2lv : W2mu;
    float*       Q  = g_Q[head][ks];
    const size_t HS = (size_t)B_ * H2_;

    const int tid  = threadIdx.x;
    const int wid  = tid >> 5,  lane = tid & 31;
    const int wm   = wid >> 2,  wn   = wid & 3;
    const int lg   = lane >> 2, lt   = lane & 3;

    const int ar = tid >> 2, akq = tid & 3;
    const int a_mt   = ar >> 4;
    const int a_slot = ((ar >> 3) & 1) + 2 * (akq >> 1);
    const int a_lane = 4 * (ar & 7) + 2 * (akq & 1);
    const size_t aoff = (size_t)(m0 + ar) * H2_ + kb + akq * 4;
    const int bkp = tid >> 5, bn2b = tid & 31;
    const int b_lt = bkp & 3, b_slot = bkp >> 2;
    const float* Wp = W + (size_t)(kb + 2 * bkp) * YD;

    float acc[2][4][4] = {};
    float4 hh0, hh1, hh2, hh3, bv4;
    float2 wu0[2], wu1[2];

    #define G2_LOAD(ch) do { \
        hh0 = *(const float4*)(Hb + 0 * HS + aoff + (ch) * 16); \
        hh1 = *(const float4*)(Hb + 1 * HS + aoff + (ch) * 16); \
        hh2 = *(const float4*)(Hb + 2 * HS + aoff + (ch) * 16); \
        hh3 = *(const float4*)(Hb + 3 * HS + aoff + (ch) * 16); \
        bv4 = *(const float4*)(b1 + kb + akq * 4 + (ch) * 16); \
        _Pragma("unroll") \
        for (int u = 0; u < 2; u++) { \
            int n = 2 * (bn2b + 32 * u); \
            wu0[u] = *(const float2*)(Wp + (size_t)(ch) * 16 * YD + n); \
            wu1[u] = *(const float2*)(Wp + (size_t)(ch) * 16 * YD + YD + n); \
        } \
    } while (0)

    #define G2_STAGE(bf) do { \
        float e0 = fmaxf(hh0.x + hh1.x + hh2.x + hh3.x + bv4.x, 0.0f); \
        float e1 = fmaxf(hh0.y + hh1.y + hh2.y + hh3.y + bv4.y, 0.0f); \
        float e2 = fmaxf(hh0.z + hh1.z + hh2.z + hh3.z + bv4.z, 0.0f); \
        float e3 = fmaxf(hh0.w + hh1.w + hh2.w + hh3.w + bv4.w, 0.0f); \
        uint32_t h01, l01, h23, l23; \
        split_pack(e0, e1, h01, l01); \
        split_pack(e2, e3, h23, l23); \
        int ai = (((bf) * 4 + a_mt) * 4 + a_slot) * APITCH + a_lane; \
        Ah[ai] = h01; Ah[ai + 1] = h23; \
        Al[ai] = l01; Al[ai + 1] = l23; \
        _Pragma("unroll") \
        for (int u = 0; u < 2; u++) { \
            _Pragma("unroll") \
            for (int j = 0; j < 2; j++) { \
                int n = 2 * (bn2b + 32 * u) + j; \
                int nt = n >> 3; \
                float vk0 = j ? wu0[u].y : wu0[u].x; \
                float vk1 = j ? wu1[u].y : wu1[u].x; \
                uint32_t bhv, blv; \
                split_pack(vk0, vk1, bhv, blv); \
                int bi = (((bf) * 16 + nt) * 2 + b_slot) * APITCH + 4 * (n & 7) + b_lt; \
                Bh[bi] = bhv; Bl[bi] = blv; \
            } \
        } \
    } while (0)

    G2_LOAD(0);
    G2_STAGE(0);
    G2_LOAD(1);
    __syncthreads();

    for (int ch = 0; ch < 4; ch++) {
        const int bfc = ch & 1;
        if (ch + 1 < 4) G2_STAGE((ch + 1) & 1);
        if (ch + 2 < 4) G2_LOAD(ch + 2);

        uint32_t Af[2][4], Afl[2][4];
        #pragma unroll
        for (int mf = 0; mf < 2; mf++) {
            int mt = wm * 2 + mf;
            int base = ((bfc * 4 + mt) * 4) * APITCH + lane;
            #pragma unroll
            for (int s = 0; s < 4; s++) {
                Af [mf][s] = Ah[base + s * APITCH];
                Afl[mf][s] = Al[base + s * APITCH];
            }
        }
        uint32_t Bf[4][2], Bfl[4][2];
        #pragma unroll
        for (int nf = 0; nf < 4; nf++) {
            int nt = wn * 4 + nf;
            int base = ((bfc * 16 + nt) * 2) * APITCH + lane;
            #pragma unroll
            for (int s = 0; s < 2; s++) {
                Bf [nf][s] = Bh[base + s * APITCH];
                Bfl[nf][s] = Bl[base + s * APITCH];
            }
        }
        #pragma unroll
        for (int mf = 0; mf < 2; mf++)
            #pragma unroll
            for (int nf = 0; nf < 4; nf++) {
                MMA16(acc[mf][nf], Af[mf],  Bf[nf]);
                MMA16(acc[mf][nf], Af[mf],  Bfl[nf]);
                MMA16(acc[mf][nf], Afl[mf], Bf[nf]);
            }
        __syncthreads();
    }

    #pragma unroll
    for (int mf = 0; mf < 2; mf++) {
        int row0 = m0 + wm * 32 + mf * 16 + lg;
        #pragma unroll
        for (int nf = 0; nf < 4; nf++) {
            int col = (wn * 4 + nf) * 8 + lt * 2;
            *(float2*)(Q + (size_t)row0 * YD + col)       = make_float2(acc[mf][nf][0], acc[mf][nf][1]);
            *(float2*)(Q + (size_t)(row0 + 8) * YD + col) = make_float2(acc[mf][nf][2], acc[mf][nf][3]);
        }
    }
}

// ---------------------------------------------------------------------------
// Kernel C (REDESIGNED): one row per block, grid 512 x 128 thr.
// Each thread owns one d: 16 g_Q loads + 32 Sy-partial loads, all independent.
// Deterministic 128-wide shared tree reduce; ticketed last block finalizes.
// negative == all_probs exactly in fp32 (511 + e^-20 == 511; log(B-1) cancels)
// ---------------------------------------------------------------------------
__global__ __launch_bounds__(128) void k_rows_final(
    const float* __restrict__ Y,
    const float* __restrict__ b2mu, const float* __restrict__ b2lv,
    float* __restrict__ out, int out_size)
{
    __shared__ double sp[128];
    __shared__ double sa[128];
    __shared__ bool s_last;

    const int i = blockIdx.x;      // row
    const int d = threadIdx.x;     // dim element
    const int idx = i * YD + d;

    // fold y column stats for this d (independent loads)
    double sy = 0.0, sy2 = 0.0;
    #pragma unroll
    for (int p = 0; p < NPART; p++) { sy += g_SyP[p][d]; sy2 += g_Sy2P[p][d]; }

    float muf = b2mu[d];
    float sf  = b2lv[d];
    #pragma unroll
    for (int j = 0; j < KS2; j++) {
        muf += g_Q[0][j][idx];
        sf  += g_Q[1][j][idx];
    }
    float lvf = tanhf(sf);
    float ivf = expf(-lvf);
    float yf  = Y[idx];

    float dmy = muf - yf;
    double pos = (double)fmaf(-0.5f * dmy * dmy, ivf, -0.5f * lvf);

    double mu = (double)muf;
    double tq = fma(mu, fma(512.0, mu, -2.0 * sy), sy2);
    double row = fma(-0.5 * (double)ivf, tq, -256.0 * (double)lvf);

    sp[d] = pos;
    sa[d] = row;
    __syncthreads();
    #pragma unroll
    for (int s = 64; s > 0; s >>= 1) {
        if (d < s) { sp[d] += sp[d + s]; sa[d] += sa[d + s]; }
        __syncthreads();
    }
    if (d == 0) {
        g_pos_row[i] = sp[0];
        g_all_row[i] = sa[0];
        __threadfence();
    }
    __syncthreads();

    if (d == 0) {
        unsigned old = atomicAdd(&g_ctr, 1u);
        s_last = (old == (unsigned)(gridDim.x - 1));
    }
    __syncthreads();
    if (!s_last) return;

    // last block: deterministic final reduce over 512 rows
    double p0 = 0.0, a0 = 0.0;
    #pragma unroll
    for (int j = d; j < B_; j += 128) { p0 += g_pos_row[j]; a0 += g_all_row[j]; }
    __syncthreads();
    sp[d] = p0;
    sa[d] = a0;
    __syncthreads();
    #pragma unroll
    for (int s = 64; s > 0; s >>= 1) {
        if (d < s) { sp[d] += sp[d + s]; sa[d] += sa[d + s]; }
        __syncthreads();
    }
    if (d == 0) {
        out[0] = (float)(sp[0] / 512.0 - sa[0] / (512.0 * 512.0));
        g_ctr = 0;  // reset for next graph replay
    }
    for (int k = d + 1; k < out_size; k += 128) out[k] = 0.0f;
}

// ---------------------------------------------------------------------------
extern "C" void kernel_launch(void* const* d_in, const int* in_sizes, int n_in,
                              void* d_out, int out_size)
{
    const float* x   = (const float*)d_in[0];
    const float* y   = (const float*)d_in[1];
    const float* w1m = (const float*)d_in[2];
    const float* b1m = (const float*)d_in[3];
    const float* w2m = (const float*)d_in[4];
    const float* b2m = (const float*)d_in[5];
    const float* w1l = (const float*)d_in[6];
    const float* b1l = (const float*)d_in[7];
    const float* w2l = (const float*)d_in[8];
    const float* b2l = (const float*)d_in[9];

    k_gemm1_mma<<<128 + NPART, 512>>>(x, y, w1m, w1l);
    k_gemm2_mma<<<128, 256>>>(b1m, b1l, w2m, w2l);
    k_rows_final<<<B_, 128>>>(y, b2m, b2l, (float*)d_out, out_size);
}

// round 16
// speedup vs baseline: 1.3135x; 1.0692x over previous
#include <cuda_runtime.h>
#include <cuda_fp16.h>
#include <math.h>
#include <stdint.h>

#define B_  512
#define XD  768
#define YD  128
#define H2_ 512
#define NPART 16
#define KS1 4          // gemm1 K-split (768/4 = 192)
#define KS2 8          // gemm2 K-split (512/8 = 64)
#define APITCH 33

__device__ float  g_H[2][KS1][B_ * H2_];   // gemm1 raw partials
__device__ float  g_Q[2][KS2][B_ * YD];    // gemm2 raw partials
__device__ double g_SyP [NPART][YD];
__device__ double g_Sy2P[NPART][YD];
__device__ double g_pos_row[B_];
__device__ double g_all_row[B_];
__device__ unsigned g_ctr = 0;

// ---------------- fp16 2-term split (Markidis): x = h + l ----------------
__device__ __forceinline__ void split_pack(float x0, float x1,
                                           uint32_t &hi, uint32_t &lo) {
    __half h0 = __float2half_rn(x0), h1 = __float2half_rn(x1);
    float r0 = x0 - __half2float(h0), r1 = x1 - __half2float(h1);
    __half l0 = __float2half_rn(r0), l1 = __float2half_rn(r1);
    __half2 H = __halves2half2(h0, h1), L = __halves2half2(l0, l1);
    hi = *(uint32_t*)&H; lo = *(uint32_t*)&L;
}

#define MMA16(c, A, B) \
    asm volatile("mma.sync.aligned.m16n8k16.row.col.f32.f16.f16.f32 " \
        "{%0,%1,%2,%3},{%4,%5,%6,%7},{%8,%9},{%0,%1,%2,%3};" \
        : "+f"((c)[0]), "+f"((c)[1]), "+f"((c)[2]), "+f"((c)[3]) \
        : "r"((A)[0]), "r"((A)[1]), "r"((A)[2]), "r"((A)[3]), \
          "r"((B)[0]), "r"((B)[1]))

// ---------------------------------------------------------------------------
// Kernel A: blocks 0..127 = GEMM1 partials via 3x-fp16 HMMA m16n8k16,
// **1024 thr, 32 warps** (8M x 4N, warp tile 16x32) on a 128x128 tile,
// K=192 slice, 12 chunks of k16. Same smem fragment layout as R11.
// blocks 128..143 = y column stats (first 128 threads only).
// ---------------------------------------------------------------------------
__global__ __launch_bounds__(1024) void k_gemm1_mma(
    const float* __restrict__ X, const float* __restrict__ Y,
    const float* __restrict__ Wmu, const float* __restrict__ Wlv)
{
    const int b = blockIdx.x;
    if (b >= 128) {
        const int p = b - 128;
        const int d = threadIdx.x;
        if (d < YD) {
            const int j0 = p * (B_ / NPART);
            double sy0 = 0, sy1 = 0, s20 = 0, s21 = 0;
            #pragma unroll 4
            for (int j = j0; j < j0 + B_ / NPART; j += 2) {
                double v0 = (double)Y[j * YD + d], v1 = (double)Y[(j + 1) * YD + d];
                sy0 += v0; s20 = fma(v0, v0, s20);
                sy1 += v1; s21 = fma(v1, v1, s21);
            }
            g_SyP[p][d] = sy0 + sy1; g_Sy2P[p][d] = s20 + s21;
        }
        return;
    }

    __shared__ uint32_t Ah[2 * 8 * 4 * APITCH], Al[2 * 8 * 4 * APITCH];
    __shared__ uint32_t Bh[2 * 16 * 2 * APITCH], Bl[2 * 16 * 2 * APITCH];

    const int head = b & 1;
    const int ks   = (b >> 1) & 3;
    const int t4   = b >> 3;
    const int m0   = (t4 >> 2) * 128;
    const int n0   = (t4 & 3) * 128;
    const int kb   = ks * 192;
    const float* W = head ? Wlv : Wmu;
    float* P       = &g_H[head][ks][0];

    const int tid  = threadIdx.x;
    const int wid  = tid >> 5,  lane = tid & 31;
    const int wm   = wid >> 2,  wn   = wid & 3;   // wm 0..7, wn 0..3
    const int lg   = lane >> 2, lt   = lane & 3;

    // A loader: ar = tid>>3 (row 0..127), ap = tid&7 (k-pair 0..7)
    const int ar = tid >> 3, ap = tid & 7;
    const int a_mt   = ar >> 4;
    const int a_slot = ((ar >> 3) & 1) + 2 * (ap >> 2);
    const int a_lane = 4 * (ar & 7) + (ap & 3);
    const float* Xp = X + (size_t)(m0 + ar) * XD + kb + ap * 2;
    // B loader: bn = tid&127 (n 0..127), bkp = tid>>7 (k-pair 0..7)
    const int bn = tid & 127, bkp = tid >> 7;
    const int b_lt = bkp & 3, b_slot = bkp >> 2;
    const int b_nt = bn >> 3;
    const int b_pl = 4 * (bn & 7) + b_lt;
    const float* Wp = W + (size_t)(kb + 2 * bkp) * H2_ + n0 + bn;

    float acc[4][4] = {};   // [nf][4], single mf
    float2 xa2; float wv0, wv1;

    #define G1_LOAD(ch) do { \
        xa2 = *(const float2*)(Xp + (ch) * 16); \
        wv0 = Wp[(size_t)(ch) * 16 * H2_]; \
        wv1 = Wp[(size_t)(ch) * 16 * H2_ + H2_]; \
    } while (0)

    #define G1_STAGE(bf) do { \
        uint32_t ah, al; \
        split_pack(xa2.x, xa2.y, ah, al); \
        int ai = (((bf) * 8 + a_mt) * 4 + a_slot) * APITCH + a_lane; \
        Ah[ai] = ah; Al[ai] = al; \
        uint32_t bhv, blv; \
        split_pack(wv0, wv1, bhv, blv); \
        int bi = (((bf) * 16 + b_nt) * 2 + b_slot) * APITCH + b_pl; \
        Bh[bi] = bhv; Bl[bi] = blv; \
    } while (0)

    G1_LOAD(0);
    G1_STAGE(0);
    G1_LOAD(1);
    __syncthreads();

    for (int ch = 0; ch < 12; ch++) {
        const int bfc = ch & 1;
        if (ch + 1 < 12) G1_STAGE((ch + 1) & 1);
        if (ch + 2 < 12) G1_LOAD(ch + 2);

        uint32_t Af[4], Afl[4];
        {
            int base = ((bfc * 8 + wm) * 4) * APITCH + lane;
            #pragma unroll
            for (int s = 0; s < 4; s++) {
                Af [s] = Ah[base + s * APITCH];
                Afl[s] = Al[base + s * APITCH];
            }
        }
        uint32_t Bf[4][2], Bfl[4][2];
        #pragma unroll
        for (int nf = 0; nf < 4; nf++) {
            int nt = wn * 4 + nf;
            int base = ((bfc * 16 + nt) * 2) * APITCH + lane;
            #pragma unroll
            for (int s = 0; s < 2; s++) {
                Bf [nf][s] = Bh[base + s * APITCH];
                Bfl[nf][s] = Bl[base + s * APITCH];
            }
        }
        #pragma unroll
        for (int nf = 0; nf < 4; nf++) {
            MMA16(acc[nf], Af,  Bf[nf]);
            MMA16(acc[nf], Af,  Bfl[nf]);
            MMA16(acc[nf], Afl, Bf[nf]);
        }
        __syncthreads();
    }

    {
        int row0 = m0 + wm * 16 + lg;
        #pragma unroll
        for (int nf = 0; nf < 4; nf++) {
            int col = n0 + wn * 32 + nf * 8 + lt * 2;
            *(float2*)(P + (size_t)row0 * H2_ + col)       = make_float2(acc[nf][0], acc[nf][1]);
            *(float2*)(P + (size_t)(row0 + 8) * H2_ + col) = make_float2(acc[nf][2], acc[nf][3]);
        }
    }
}

// ---------------------------------------------------------------------------
// GEMM2 (R11-proven): Q[head][ks] = relu(sum_j H_j + b1) @ W2[kslice].
// Block: 64x128 tile, K=64 slice (4 chunks of k16), 256 thr, 8 warps
// (2M x 4N, warp tile 32x32), double-buffered. grid 128 = 2 x 8 M x 8 K.
// ---------------------------------------------------------------------------
__global__ __launch_bounds__(256) void k_gemm2_mma(
    const float* __restrict__ b1mu, const float* __restrict__ b1lv,
    const float* __restrict__ W2mu, const float* __restrict__ W2lv)
{
    __shared__ uint32_t Ah[2 * 4 * 4 * APITCH], Al[2 * 4 * 4 * APITCH];
    __shared__ uint32_t Bh[2 * 16 * 2 * APITCH], Bl[2 * 16 * 2 * APITCH];

    const int b    = blockIdx.x;
    const int head = b & 1;
    const int ks   = (b >> 1) & 7;
    const int m0   = (b >> 4) * 64;
    const int kb   = ks * 64;
    const float* Hb = &g_H[head][0][0];
    const float* b1 = head ? b1lv : b1mu;
    const float* W  = head ? W2lv : W2mu;
    float*       Q  = g_Q[head][ks];
    const size_t HS = (size_t)B_ * H2_;

    const int tid  = threadIdx.x;
    const int wid  = tid >> 5,  lane = tid & 31;
    const int wm   = wid >> 2,  wn   = wid & 3;
    const int lg   = lane >> 2, lt   = lane & 3;

    const int ar = tid >> 2, akq = tid & 3;
    const int a_mt   = ar >> 4;
    const int a_slot = ((ar >> 3) & 1) + 2 * (akq >> 1);
    const int a_lane = 4 * (ar & 7) + 2 * (akq & 1);
    const size_t aoff = (size_t)(m0 + ar) * H2_ + kb + akq * 4;
    const int bkp = tid >> 5, bn2b = tid & 31;
    const int b_lt = bkp & 3, b_slot = bkp >> 2;
    const float* Wp = W + (size_t)(kb + 2 * bkp) * YD;

    float acc[2][4][4] = {};
    float4 hh0, hh1, hh2, hh3, bv4;
    float2 wu0[2], wu1[2];

    #define G2_LOAD(ch) do { \
        hh0 = *(const float4*)(Hb + 0 * HS + aoff + (ch) * 16); \
        hh1 = *(const float4*)(Hb + 1 * HS + aoff + (ch) * 16); \
        hh2 = *(const float4*)(Hb + 2 * HS + aoff + (ch) * 16); \
        hh3 = *(const float4*)(Hb + 3 * HS + aoff + (ch) * 16); \
        bv4 = *(const float4*)(b1 + kb + akq * 4 + (ch) * 16); \
        _Pragma("unroll") \
        for (int u = 0; u < 2; u++) { \
            int n = 2 * (bn2b + 32 * u); \
            wu0[u] = *(const float2*)(Wp + (size_t)(ch) * 16 * YD + n); \
            wu1[u] = *(const float2*)(Wp + (size_t)(ch) * 16 * YD + YD + n); \
        } \
    } while (0)

    #define G2_STAGE(bf) do { \
        float e0 = fmaxf(hh0.x + hh1.x + hh2.x + hh3.x + bv4.x, 0.0f); \
        float e1 = fmaxf(hh0.y + hh1.y + hh2.y + hh3.y + bv4.y, 0.0f); \
        float e2 = fmaxf(hh0.z + hh1.z + hh2.z + hh3.z + bv4.z, 0.0f); \
        float e3 = fmaxf(hh0.w + hh1.w + hh2.w + hh3.w + bv4.w, 0.0f); \
        uint32_t h01, l01, h23, l23; \
        split_pack(e0, e1, h01, l01); \
        split_pack(e2, e3, h23, l23); \
        int ai = (((bf) * 4 + a_mt) * 4 + a_slot) * APITCH + a_lane; \
        Ah[ai] = h01; Ah[ai + 1] = h23; \
        Al[ai] = l01; Al[ai + 1] = l23; \
        _Pragma("unroll") \
        for (int u = 0; u < 2; u++) { \
            _Pragma("unroll") \
            for (int j = 0; j < 2; j++) { \
                int n = 2 * (bn2b + 32 * u) + j; \
                int nt = n >> 3; \
                float vk0 = j ? wu0[u].y : wu0[u].x; \
                float vk1 = j ? wu1[u].y : wu1[u].x; \
                uint32_t bhv, blv; \
                split_pack(vk0, vk1, bhv, blv); \
                int bi = (((bf) * 16 + nt) * 2 + b_slot) * APITCH + 4 * (n & 7) + b_lt; \
                Bh[bi] = bhv; Bl[bi] = blv; \
            } \
        } \
    } while (0)

    G2_LOAD(0);
    G2_STAGE(0);
    G2_LOAD(1);
    __syncthreads();

    for (int ch = 0; ch < 4; ch++) {
        const int bfc = ch & 1;
        if (ch + 1 < 4) G2_STAGE((ch + 1) & 1);
        if (ch + 2 < 4) G2_LOAD(ch + 2);

        uint32_t Af[2][4], Afl[2][4];
        #pragma unroll
        for (int mf = 0; mf < 2; mf++) {
            int mt = wm * 2 + mf;
            int base = ((bfc * 4 + mt) * 4) * APITCH + lane;
            #pragma unroll
            for (int s = 0; s < 4; s++) {
                Af [mf][s] = Ah[base + s * APITCH];
                Afl[mf][s] = Al[base + s * APITCH];
            }
        }
        uint32_t Bf[4][2], Bfl[4][2];
        #pragma unroll
        for (int nf = 0; nf < 4; nf++) {
            int nt = wn * 4 + nf;
            int base = ((bfc * 16 + nt) * 2) * APITCH + lane;
            #pragma unroll
            for (int s = 0; s < 2; s++) {
                Bf [nf][s] = Bh[base + s * APITCH];
                Bfl[nf][s] = Bl[base + s * APITCH];
            }
        }
        #pragma unroll
        for (int mf = 0; mf < 2; mf++)
            #pragma unroll
            for (int nf = 0; nf < 4; nf++) {
                MMA16(acc[mf][nf], Af[mf],  Bf[nf]);
                MMA16(acc[mf][nf], Af[mf],  Bfl[nf]);
                MMA16(acc[mf][nf], Afl[mf], Bf[nf]);
            }
        __syncthreads();
    }

    #pragma unroll
    for (int mf = 0; mf < 2; mf++) {
        int row0 = m0 + wm * 32 + mf * 16 + lg;
        #pragma unroll
        for (int nf = 0; nf < 4; nf++) {
            int col = (wn * 4 + nf) * 8 + lt * 2;
            *(float2*)(Q + (size_t)row0 * YD + col)       = make_float2(acc[mf][nf][0], acc[mf][nf][1]);
            *(float2*)(Q + (size_t)(row0 + 8) * YD + col) = make_float2(acc[mf][nf][2], acc[mf][nf][3]);
        }
    }
}

// ---------------------------------------------------------------------------
// Kernel C (R11-proven): epilogue + per-row reductions + final scalar.
// grid 128 x 128 thr; one warp per row (4 rows/block), last-block ticket.
// negative == all_probs exactly in fp32 (511 + e^-20 == 511; log(B-1) cancels)
// ---------------------------------------------------------------------------
__global__ __launch_bounds__(128) void k_rows_final(
    const float* __restrict__ Y,
    const float* __restrict__ b2mu, const float* __restrict__ b2lv,
    float* __restrict__ out, int out_size)
{
    __shared__ double sSy[YD];
    __shared__ double sSy2[YD];
    __shared__ bool s_last;

    const int tid = threadIdx.x;
    {
        double s = 0.0, s2 = 0.0;
        #pragma unroll
        for (int p = 0; p < NPART; p++) { s += g_SyP[p][tid]; s2 += g_Sy2P[p][tid]; }
        sSy[tid] = s; sSy2[tid] = s2;
    }
    __syncthreads();

    const int lane = tid & 31;
    const int wid  = tid >> 5;
    const int i    = blockIdx.x * 4 + wid;

    double pos = 0.0, row = 0.0;
    #pragma unroll
    for (int q = 0; q < 4; q++) {
        int d = q * 32 + lane;
        int idx = i * YD + d;
        float muf = b2mu[d];
        float sf  = b2lv[d];
        #pragma unroll
        for (int j = 0; j < KS2; j++) {
            muf += g_Q[0][j][idx];
            sf  += g_Q[1][j][idx];
        }
        float lvf = tanhf(sf);
        float ivf = expf(-lvf);
        float yf  = Y[idx];

        float dmy = muf - yf;
        pos += (double)fmaf(-0.5f * dmy * dmy, ivf, -0.5f * lvf);

        double mu = (double)muf;
        double tq = fma(mu, fma(512.0, mu, -2.0 * sSy[d]), sSy2[d]);
        row = fma(-0.5 * (double)ivf, tq, row);
        row = fma(-256.0, (double)lvf, row);
    }
    #pragma unroll
    for (int off = 16; off > 0; off >>= 1) {
        pos += __shfl_down_sync(0xffffffffu, pos, off);
        row += __shfl_down_sync(0xffffffffu, row, off);
    }
    if (lane == 0) {
        g_pos_row[i] = pos;
        g_all_row[i] = row;
        __threadfence();
    }
    __syncthreads();

    if (tid == 0) {
        unsigned old = atomicAdd(&g_ctr, 1u);
        s_last = (old == gridDim.x - 1);
    }
    __syncthreads();
    if (!s_last) return;

    double p0 = 0.0, a0 = 0.0;
    #pragma unroll
    for (int j = tid; j < B_; j += 128) { p0 += g_pos_row[j]; a0 += g_all_row[j]; }
    sSy[tid]  = p0;
    sSy2[tid] = a0;
    __syncthreads();
    #pragma unroll
    for (int s = 64; s > 0; s >>= 1) {
        if (tid < s) { sSy[tid] += sSy[tid + s]; sSy2[tid] += sSy2[tid + s]; }
        __syncthreads();
    }
    if (tid == 0) {
        out[0] = (float)(sSy[0] / 512.0 - sSy2[0] / (512.0 * 512.0));
        g_ctr = 0;
    }
    for (int k = tid + 1; k < out_size; k += 128) out[k] = 0.0f;
}

// ---------------------------------------------------------------------------
extern "C" void kernel_launch(void* const* d_in, const int* in_sizes, int n_in,
                              void* d_out, int out_size)
{
    const float* x   = (const float*)d_in[0];
    const float* y   = (const float*)d_in[1];
    const float* w1m = (const float*)d_in[2];
    const float* b1m = (const float*)d_in[3];
    const float* w2m = (const float*)d_in[4];
    const float* b2m = (const float*)d_in[5];
    const float* w1l = (const float*)d_in[6];
    const float* b1l = (const float*)d_in[7];
    const float* w2l = (const float*)d_in[8];
    const float* b2l = (const float*)d_in[9];

    k_gemm1_mma<<<128 + NPART, 1024>>>(x, y, w1m, w1l);
    k_gemm2_mma<<<128, 256>>>(b1m, b1l, w2m, w2l);
    k_rows_final<<<B_ / 4, 128>>>(y, b2m, b2l, (float*)d_out, out_size);
}